// round 15
// baseline (speedup 1.0000x reference)
#include <cuda_runtime.h>
#include <cuda.h>
#include <cuda_fp16.h>
#include <cstdint>

// ============================================================================
// Problem constants
// ============================================================================
#define IN_DIM   4096
#define OUT_DIM  4096
#define M_ROWS   8192          // 4 * 2048
#define RANK     16
#define BLOCK_Q  64            // NF4 block size
#define LORA_SCALE 2.0f        // alpha / rank

// GEMM tiling (fp16 operands, fp32 accum)
#define BM 128
#define BN 128
#define BKH 64                 // halves per K chunk (= 128 B per row)
#define NCHUNK (IN_DIM / BKH)  // 64
#define STAGES 3
#define THREADS 256

#define A_TILE_BYTES (BM * 128)                    // 16384
#define B_TILE_BYTES (BN * 128)                    // 16384
#define STAGE_BYTES (A_TILE_BYTES + B_TILE_BYTES)  // 32768
// dynamic smem: up-to-1023B align pad + 3 stages + mbarriers
#define SMEM_ALLOC (1024 + STAGES * STAGE_BYTES + 64)   // 99392 -> 2 CTAs/SM

#define TILES_M (M_ROWS / BM)   // 64
#define TILES_N (OUT_DIM / BN)  // 32
#define GROUP_M 8

// prep_x: 4 independent float4 loads per thread (MLP=4)
#define PX_PER_THREAD 4
#define PX_ELEMS (M_ROWS * IN_DIM / 4)                       // 8M float4
#define PX_BLOCKS (PX_ELEMS / (256 * PX_PER_THREAD))         // 8192

// ============================================================================
// Scratch (device globals — no runtime allocation allowed)
// ============================================================================
__device__ __align__(1024) __half g_wh[(size_t)OUT_DIM * IN_DIM];   // 32 MB
__device__ __align__(1024) __half g_xh[(size_t)M_ROWS * IN_DIM];    // 64 MB

__constant__ float c_nf4[16] = {
    -1.0f, -0.6961928009986877f, -0.5250730514526367f, -0.39491748809814453f,
    -0.28444138169288635f, -0.18477343022823334f, -0.09105003625154495f, 0.0f,
    0.07958029955625534f, 0.16093020141124725f, 0.24611230194568634f,
    0.33791524171829224f, 0.44070982933044434f, 0.5626170039176941f,
    0.7229568362236328f, 1.0f};

// ============================================================================
// PTX helpers (sm_90 baseline features: TMA, mbarrier; sm_80: ldmatrix, mma)
// ============================================================================
__device__ __forceinline__ uint32_t smem_u32(const void* p) {
    uint32_t a;
    asm("{ .reg .u64 t; cvta.to.shared.u64 t, %1; cvt.u32.u64 %0, t; }" : "=r"(a) : "l"(p));
    return a;
}

#define MBAR_INIT(a, n) \
    asm volatile("mbarrier.init.shared.b64 [%0], %1;" :: "r"(a), "r"(n) : "memory")
#define MBAR_EXPECT_TX(a, b) \
    asm volatile("mbarrier.arrive.expect_tx.shared.b64 _, [%0], %1;" :: "r"(a), "r"(b) : "memory")
#define MBAR_ARRIVE(a) \
    asm volatile("mbarrier.arrive.release.cta.shared::cta.b64 _, [%0];" :: "r"(a) : "memory")

// Order prior generic-proxy smem accesses (LDSM reads, mbarrier.init stores)
// before subsequent async-proxy accesses (TMA writes) to the same locations.
#define FENCE_PROXY_ASYNC() \
    asm volatile("fence.proxy.async.shared::cta;" ::: "memory")

#define MBAR_WAIT(a, ph) do {                                                   \
    uint32_t _m = (a), _p = (ph), _d;                                           \
    asm volatile("{\n\t.reg .pred p;\n\t"                                       \
        "mbarrier.try_wait.parity.acquire.cta.shared::cta.b64 p, [%1], %2;\n\t" \
        "selp.b32 %0, 1, 0, p;\n\t}"                                            \
        : "=r"(_d) : "r"(_m), "r"(_p) : "memory");                              \
    if (!_d) {                                                                  \
        asm volatile("{\n\t.reg .pred P1;\n\t"                                  \
            "WL_%=:\n\t"                                                        \
            "mbarrier.try_wait.parity.acquire.cta.shared::cta.b64 P1, [%0], %1, 0x989680;\n\t" \
            "@P1 bra.uni WD_%=;\n\t"                                            \
            "bra.uni WL_%=;\n\t"                                                \
            "WD_%=:\n\t}"                                                       \
            :: "r"(_m), "r"(_p) : "memory");                                    \
    }                                                                           \
} while (0)

__device__ __forceinline__ void tma2d(uint32_t dst, const CUtensorMap* m,
                                      int cx, int cy, uint32_t mbar) {
    asm volatile(
        "cp.async.bulk.tensor.2d.shared::cta.global.tile.mbarrier::complete_tx::bytes "
        "[%0], [%1, {%2, %3}], [%4];"
        :: "r"(dst), "l"(m), "r"(cx), "r"(cy), "r"(mbar) : "memory");
}

#define LDSM_X4(r0, r1, r2, r3, addr)                                         \
    asm volatile("ldmatrix.sync.aligned.m8n8.x4.shared.b16 {%0,%1,%2,%3}, [%4];" \
        : "=r"(r0), "=r"(r1), "=r"(r2), "=r"(r3) : "r"(addr))

__device__ __forceinline__ void mma_fp16(float& d0, float& d1, float& d2, float& d3,
                                         uint32_t a0, uint32_t a1, uint32_t a2, uint32_t a3,
                                         uint32_t b0, uint32_t b1) {
    asm volatile(
        "mma.sync.aligned.m16n8k16.row.col.f32.f16.f16.f32 "
        "{%0,%1,%2,%3}, {%4,%5,%6,%7}, {%8,%9}, {%0,%1,%2,%3};"
        : "+f"(d0), "+f"(d1), "+f"(d2), "+f"(d3)
        : "r"(a0), "r"(a1), "r"(a2), "r"(a3), "r"(b0), "r"(b1));
}

// ============================================================================
// Prep kernels
// ============================================================================
// W_eff[o][i] = nf4[code]*scale + 2 * sum_r lb[o][r]*la[r][i]  -> fp16
// LoRA sum computed in packed half2 (16 HFMA2 vs 32 FFMA): the LoRA term is
// ~1e-3 magnitude vs base ~1e-2, so fp16 accumulation error (~5e-7 abs) is
// invisible next to the final fp16 quantization of W itself.
__global__ void __launch_bounds__(256) prep_w_kernel(
    const int* __restrict__ codes, const float* __restrict__ scales,
    const float* __restrict__ la, const float* __restrict__ lb,
    __half* __restrict__ wh) {
    __shared__ __half2 la_s[RANK][256];   // [r][t] = (la[r][i0+2t], la[r][i0+2t+1])
    __shared__ __half2 lb_s[32][RANK];    // broadcast pair, pre-scaled by LORA_SCALE
    __shared__ float nf4_s[16];
    const int t  = threadIdx.x;
    const int i0 = blockIdx.x * 512;
    const int o0 = blockIdx.y * 32;
    if (t < 16) nf4_s[t] = c_nf4[t];
#pragma unroll
    for (int r = 0; r < RANK; r++) {
        float2 v = reinterpret_cast<const float2*>(la + r * IN_DIM + i0)[t];
        la_s[r][t] = __floats2half2_rn(v.x, v.y);
    }
    for (int j = t; j < 32 * RANK; j += 256) {
        float b = LORA_SCALE * lb[(size_t)(o0 + (j >> 4)) * RANK + (j & 15)];
        lb_s[j >> 4][j & 15] = __float2half2_rn(b);
    }
    __syncthreads();

    __half2 a2[RANK];
#pragma unroll
    for (int r = 0; r < RANK; r++)
        a2[r] = la_s[r][t];

    const int i = i0 + 2 * t;
#pragma unroll 4
    for (int oo = 0; oo < 32; oo++) {
        const int o = o0 + oo;
        const int2 cd = *reinterpret_cast<const int2*>(codes + (size_t)o * IN_DIM + i);
        const float s = scales[o * (IN_DIM / BLOCK_Q) + (i >> 6)];
        __half2 acc0 = __float2half2_rn(0.0f);
        __half2 acc1 = __float2half2_rn(0.0f);
#pragma unroll
        for (int r = 0; r < RANK; r += 2) {
            acc0 = __hfma2(lb_s[oo][r],     a2[r],     acc0);
            acc1 = __hfma2(lb_s[oo][r + 1], a2[r + 1], acc1);
        }
        const __half2 acc = __hadd2(acc0, acc1);
        const float wx = fmaf(nf4_s[cd.x & 15], s, __low2float(acc));
        const float wy = fmaf(nf4_s[cd.y & 15], s, __high2float(acc));
        __half2 h = __floats2half2_rn(wx, wy);
        *reinterpret_cast<uint32_t*>(wh + (size_t)o * IN_DIM + i) =
            *reinterpret_cast<uint32_t*>(&h);
    }
}

// x (fp32) -> fp16; 4 independent float4 loads per thread (MLP=4).
__global__ void __launch_bounds__(256) prep_x_kernel(
    const float4* __restrict__ in, uint2* __restrict__ out) {
    const int base = blockIdx.x * (256 * PX_PER_THREAD) + threadIdx.x;
    float4 v[PX_PER_THREAD];
#pragma unroll
    for (int k = 0; k < PX_PER_THREAD; k++)
        v[k] = in[base + k * 256];
#pragma unroll
    for (int k = 0; k < PX_PER_THREAD; k++) {
        __half2 h0 = __floats2half2_rn(v[k].x, v[k].y);
        __half2 h1 = __floats2half2_rn(v[k].z, v[k].w);
        uint2 u;
        u.x = *reinterpret_cast<uint32_t*>(&h0);
        u.y = *reinterpret_cast<uint32_t*>(&h1);
        out[base + k * 256] = u;
    }
}

// ============================================================================
// GEMM: out[M, N] = Xh[M, K] @ Wh[N, K]^T   (mma.sync fp16, fp32 accum)
// TMA + mbarrier producer/consumer pipeline, proxy-fenced, lag-1 refill
// (round-10 kernel verbatim — tensor pipe 88.4%).
// ============================================================================
__global__ void __launch_bounds__(THREADS, 2) gemm_fp16_kernel(
    const __grid_constant__ CUtensorMap mapA,
    const __grid_constant__ CUtensorMap mapB,
    float* __restrict__ out) {
    extern __shared__ char smem[];
    const uint32_t sb = smem_u32(smem);
    const uint32_t ab = (sb + 1023u) & ~1023u;          // 1KB-aligned tile base
    const uint32_t full0  = ab + STAGES * STAGE_BYTES;  // 3 x 8B
    const uint32_t empty0 = full0 + STAGES * 8;         // 3 x 8B
    const int tid  = threadIdx.x;
    const int wid  = tid >> 5;
    const int lane = tid & 31;
    const int gid  = lane >> 2;
    const int tig  = lane & 3;

    // tile swizzle for L2 reuse
    const int bid   = blockIdx.x;
    const int group = bid / (GROUP_M * TILES_N);
    const int inb   = bid % (GROUP_M * TILES_N);
    const int mtile = group * GROUP_M + (inb % GROUP_M);
    const int ntile = inb / GROUP_M;
    const int m0 = mtile * BM;
    const int n0 = ntile * BN;

    const int wm = (wid & 1) * 64;   // 2 warps along M
    const int wn = (wid >> 1) * 32;  // 4 warps along N

    if (tid == 0) {
        for (int s = 0; s < STAGES; s++) {
            MBAR_INIT(full0 + s * 8, 1);        // completes via expect_tx + tx drain
            MBAR_INIT(empty0 + s * 8, THREADS); // all threads arrive after consuming
        }
        FENCE_PROXY_ASYNC();   // order generic-proxy init stores before TMA use
    }
    __syncthreads();

    // prologue: one thread launches TMA for chunks 0..2
    if (tid == 0) {
#pragma unroll
        for (int s = 0; s < STAGES; s++) {
            uint32_t fb = full0 + s * 8;
            MBAR_EXPECT_TX(fb, STAGE_BYTES);
            tma2d(ab + s * STAGE_BYTES,                &mapA, s * BKH, m0, fb);
            tma2d(ab + s * STAGE_BYTES + A_TILE_BYTES, &mapB, s * BKH, n0, fb);
        }
    }

    // ldmatrix address precompute (offsets within a tile)
    uint32_t a_off[4], a_x[4];
#pragma unroll
    for (int mt = 0; mt < 4; mt++) {
        int r = wm + mt * 16 + (lane & 15);
        a_off[mt] = (uint32_t)(r * 128);
        a_x[mt]   = (uint32_t)(r & 7);
    }
    const uint32_t a_hi = (uint32_t)(lane >> 4);
    uint32_t b_off[2], b_x[2];
#pragma unroll
    for (int ntp = 0; ntp < 2; ntp++) {
        int r = wn + ntp * 16 + (lane & 7) + ((lane >> 4) << 3);
        b_off[ntp] = (uint32_t)(r * 128);
        b_x[ntp]   = (uint32_t)(r & 7);
    }
    const uint32_t b_hi = (uint32_t)((lane >> 3) & 1);

    float acc[4][4][4];
#pragma unroll
    for (int mt = 0; mt < 4; mt++)
#pragma unroll
        for (int nt = 0; nt < 4; nt++)
#pragma unroll
            for (int r = 0; r < 4; r++) acc[mt][nt][r] = 0.0f;

    // mainloop: stage s = c % 3, parity ph flips each wrap
    int s = 0, ph = 0;
    for (int c = 0; c < NCHUNK; c++) {
        MBAR_WAIT(full0 + s * 8, ph);

        // lag-1 producer refill: stage of chunk c-1 receives chunk c+2.
        if (tid == 0 && c >= 1 && c + 2 < NCHUNK) {
            const int pc   = c - 1;
            const int prev = pc % STAGES;
            MBAR_WAIT(empty0 + prev * 8, (pc / STAGES) & 1);
            uint32_t fb = full0 + prev * 8;
            MBAR_EXPECT_TX(fb, STAGE_BYTES);
            tma2d(ab + prev * STAGE_BYTES,                &mapA, (pc + STAGES) * BKH, m0, fb);
            tma2d(ab + prev * STAGE_BYTES + A_TILE_BYTES, &mapB, (pc + STAGES) * BKH, n0, fb);
        }

        const uint32_t As = ab + (uint32_t)(s * STAGE_BYTES);
        const uint32_t Bs = As + A_TILE_BYTES;

#pragma unroll
        for (int ks = 0; ks < BKH / 16; ks++) {
            uint32_t a_frag[4][4];
            uint32_t b_frag[4][2];
#pragma unroll
            for (int mt = 0; mt < 4; mt++) {
                uint32_t ad = As + a_off[mt] + (((2u * ks + a_hi) ^ a_x[mt]) * 16);
                LDSM_X4(a_frag[mt][0], a_frag[mt][1], a_frag[mt][2], a_frag[mt][3], ad);
            }
#pragma unroll
            for (int ntp = 0; ntp < 2; ntp++) {
                uint32_t bd = Bs + b_off[ntp] + (((2u * ks + b_hi) ^ b_x[ntp]) * 16);
                LDSM_X4(b_frag[2 * ntp][0], b_frag[2 * ntp][1],
                        b_frag[2 * ntp + 1][0], b_frag[2 * ntp + 1][1], bd);
            }
#pragma unroll
            for (int mt = 0; mt < 4; mt++)
#pragma unroll
                for (int nt = 0; nt < 4; nt++)
                    mma_fp16(acc[mt][nt][0], acc[mt][nt][1], acc[mt][nt][2], acc[mt][nt][3],
                             a_frag[mt][0], a_frag[mt][1], a_frag[mt][2], a_frag[mt][3],
                             b_frag[nt][0], b_frag[nt][1]);
        }

        // Close the generic->async proxy WAR hazard, then release the stage.
        FENCE_PROXY_ASYNC();
        MBAR_ARRIVE(empty0 + s * 8);

        if (++s == STAGES) { s = 0; ph ^= 1; }
    }

    // epilogue: row = m0+wm+mt*16+gid(+8), col = n0+wn+nt*8+tig*2
#pragma unroll
    for (int mt = 0; mt < 4; mt++) {
        const size_t r0 = (size_t)(m0 + wm + mt * 16 + gid) * OUT_DIM;
        const size_t r1 = r0 + 8 * OUT_DIM;
#pragma unroll
        for (int nt = 0; nt < 4; nt++) {
            const int col = n0 + wn + nt * 8 + tig * 2;
            *reinterpret_cast<float2*>(out + r0 + col) =
                make_float2(acc[mt][nt][0], acc[mt][nt][1]);
            *reinterpret_cast<float2*>(out + r1 + col) =
                make_float2(acc[mt][nt][2], acc[mt][nt][3]);
        }
    }
}

// ============================================================================
// Host
// ============================================================================
typedef CUresult (*EncodeFn)(CUtensorMap*, CUtensorMapDataType, cuuint32_t, void*,
                             const cuuint64_t*, const cuuint64_t*, const cuuint32_t*,
                             const cuuint32_t*, CUtensorMapInterleave, CUtensorMapSwizzle,
                             CUtensorMapL2promotion, CUtensorMapFloatOOBfill);

static EncodeFn get_encode_fn() {
    static EncodeFn fn = nullptr;
    if (!fn) {
        void* p = nullptr;
        cudaDriverEntryPointQueryResult qr;
#if CUDART_VERSION >= 12050
        cudaGetDriverEntryPointByVersion("cuTensorMapEncodeTiled", &p, 12000,
                                         cudaEnableDefault, &qr);
#else
        cudaGetDriverEntryPoint("cuTensorMapEncodeTiled", &p, cudaEnableDefault, &qr);
#endif
        fn = (EncodeFn)p;
    }
    return fn;
}

extern "C" void kernel_launch(void* const* d_in, const int* in_sizes, int n_in,
                              void* d_out, int out_size) {
    const float* x      = (const float*)d_in[0];
    const int*   codes  = (const int*)d_in[1];
    const float* scales = (const float*)d_in[2];
    const float* la     = (const float*)d_in[3];
    const float* lb     = (const float*)d_in[4];
    float* out = (float*)d_out;

    void *wptr = nullptr, *xptr = nullptr;
    cudaGetSymbolAddress(&wptr, g_wh);
    cudaGetSymbolAddress(&xptr, g_xh);

    static bool attr_set = false;
    if (!attr_set) {
        cudaFuncSetAttribute(gemm_fp16_kernel,
                             cudaFuncAttributeMaxDynamicSharedMemorySize, SMEM_ALLOC);
        attr_set = true;
    }

    // 1) fold LoRA + NF4 dequant into W_eff (fp16)
    prep_w_kernel<<<dim3(IN_DIM / 512, OUT_DIM / 32), 256>>>(
        codes, scales, la, lb, (__half*)wptr);
    // 2) x -> fp16 (MLP=4 per thread)
    prep_x_kernel<<<PX_BLOCKS, 256>>>((const float4*)x, (uint2*)xptr);

    // 3) TMA descriptors: [K, rows] fp16, box {BKH, 128}, SW128 swizzle
    EncodeFn enc = get_encode_fn();
    CUtensorMap mA, mB;
    {
        cuuint64_t dims[2]    = {IN_DIM, M_ROWS};
        cuuint64_t strides[1] = {IN_DIM * sizeof(__half)};
        cuuint32_t box[2]     = {BKH, BM};
        cuuint32_t es[2]      = {1, 1};
        enc(&mA, CU_TENSOR_MAP_DATA_TYPE_FLOAT16, 2, xptr, dims, strides, box, es,
            CU_TENSOR_MAP_INTERLEAVE_NONE, CU_TENSOR_MAP_SWIZZLE_128B,
            CU_TENSOR_MAP_L2_PROMOTION_L2_128B, CU_TENSOR_MAP_FLOAT_OOB_FILL_NONE);
    }
    {
        cuuint64_t dims[2]    = {IN_DIM, OUT_DIM};
        cuuint64_t strides[1] = {IN_DIM * sizeof(__half)};
        cuuint32_t box[2]     = {BKH, BN};
        cuuint32_t es[2]      = {1, 1};
        enc(&mB, CU_TENSOR_MAP_DATA_TYPE_FLOAT16, 2, wptr, dims, strides, box, es,
            CU_TENSOR_MAP_INTERLEAVE_NONE, CU_TENSOR_MAP_SWIZZLE_128B,
            CU_TENSOR_MAP_L2_PROMOTION_L2_128B, CU_TENSOR_MAP_FLOAT_OOB_FILL_NONE);
    }

    // 4) single large GEMM (2048 CTAs, 2 resident per SM)
    gemm_fp16_kernel<<<TILES_M * TILES_N, THREADS, SMEM_ALLOC>>>(mA, mB, out);
}

// round 16
// speedup vs baseline: 1.0129x; 1.0129x over previous
#include <cuda_runtime.h>
#include <cuda.h>
#include <cuda_fp16.h>
#include <cstdint>

// ============================================================================
// Problem constants
// ============================================================================
#define IN_DIM   4096
#define OUT_DIM  4096
#define M_ROWS   8192          // 4 * 2048
#define RANK     16
#define BLOCK_Q  64            // NF4 block size
#define LORA_SCALE 2.0f        // alpha / rank

// GEMM tiling (fp16 operands, fp32 accum)
#define BM 128
#define BN 128
#define BKH 64                 // halves per K chunk (= 128 B per row)
#define NCHUNK (IN_DIM / BKH)  // 64
#define STAGES 3
#define THREADS 256

#define A_TILE_BYTES (BM * 128)                    // 16384
#define B_TILE_BYTES (BN * 128)                    // 16384
#define STAGE_BYTES (A_TILE_BYTES + B_TILE_BYTES)  // 32768
// dynamic smem: up-to-1023B align pad + 3 stages + mbarriers
#define SMEM_ALLOC (1024 + STAGES * STAGE_BYTES + 64)   // 99392 -> 2 CTAs/SM

#define TILES_M (M_ROWS / BM)   // 64
#define TILES_N (OUT_DIM / BN)  // 32
#define GROUP_M 8

// prep_x: 4 independent float4 loads per thread (MLP=4)
#define PX_PER_THREAD 4
#define PX_ELEMS (M_ROWS * IN_DIM / 4)                       // 8M float4
#define PX_BLOCKS (PX_ELEMS / (256 * PX_PER_THREAD))         // 8192

// ============================================================================
// Scratch (device globals — no runtime allocation allowed)
// ============================================================================
__device__ __align__(1024) __half g_wh[(size_t)OUT_DIM * IN_DIM];   // 32 MB
__device__ __align__(1024) __half g_xh[(size_t)M_ROWS * IN_DIM];    // 64 MB

__constant__ float c_nf4[16] = {
    -1.0f, -0.6961928009986877f, -0.5250730514526367f, -0.39491748809814453f,
    -0.28444138169288635f, -0.18477343022823334f, -0.09105003625154495f, 0.0f,
    0.07958029955625534f, 0.16093020141124725f, 0.24611230194568634f,
    0.33791524171829224f, 0.44070982933044434f, 0.5626170039176941f,
    0.7229568362236328f, 1.0f};

// ============================================================================
// PTX helpers (sm_90 baseline features: TMA, mbarrier; sm_80: ldmatrix, mma)
// ============================================================================
__device__ __forceinline__ uint32_t smem_u32(const void* p) {
    uint32_t a;
    asm("{ .reg .u64 t; cvta.to.shared.u64 t, %1; cvt.u32.u64 %0, t; }" : "=r"(a) : "l"(p));
    return a;
}

#define MBAR_INIT(a, n) \
    asm volatile("mbarrier.init.shared.b64 [%0], %1;" :: "r"(a), "r"(n) : "memory")
#define MBAR_EXPECT_TX(a, b) \
    asm volatile("mbarrier.arrive.expect_tx.shared.b64 _, [%0], %1;" :: "r"(a), "r"(b) : "memory")
#define MBAR_ARRIVE(a) \
    asm volatile("mbarrier.arrive.release.cta.shared::cta.b64 _, [%0];" :: "r"(a) : "memory")

// Order prior generic-proxy smem accesses (LDSM reads, mbarrier.init stores)
// before subsequent async-proxy accesses (TMA writes) to the same locations.
#define FENCE_PROXY_ASYNC() \
    asm volatile("fence.proxy.async.shared::cta;" ::: "memory")

#define MBAR_WAIT(a, ph) do {                                                   \
    uint32_t _m = (a), _p = (ph), _d;                                           \
    asm volatile("{\n\t.reg .pred p;\n\t"                                       \
        "mbarrier.try_wait.parity.acquire.cta.shared::cta.b64 p, [%1], %2;\n\t" \
        "selp.b32 %0, 1, 0, p;\n\t}"                                            \
        : "=r"(_d) : "r"(_m), "r"(_p) : "memory");                              \
    if (!_d) {                                                                  \
        asm volatile("{\n\t.reg .pred P1;\n\t"                                  \
            "WL_%=:\n\t"                                                        \
            "mbarrier.try_wait.parity.acquire.cta.shared::cta.b64 P1, [%0], %1, 0x989680;\n\t" \
            "@P1 bra.uni WD_%=;\n\t"                                            \
            "bra.uni WL_%=;\n\t"                                                \
            "WD_%=:\n\t}"                                                       \
            :: "r"(_m), "r"(_p) : "memory");                                    \
    }                                                                           \
} while (0)

__device__ __forceinline__ void tma2d(uint32_t dst, const CUtensorMap* m,
                                      int cx, int cy, uint32_t mbar) {
    asm volatile(
        "cp.async.bulk.tensor.2d.shared::cta.global.tile.mbarrier::complete_tx::bytes "
        "[%0], [%1, {%2, %3}], [%4];"
        :: "r"(dst), "l"(m), "r"(cx), "r"(cy), "r"(mbar) : "memory");
}

#define LDSM_X4(r0, r1, r2, r3, addr)                                         \
    asm volatile("ldmatrix.sync.aligned.m8n8.x4.shared.b16 {%0,%1,%2,%3}, [%4];" \
        : "=r"(r0), "=r"(r1), "=r"(r2), "=r"(r3) : "r"(addr))

__device__ __forceinline__ void mma_fp16(float& d0, float& d1, float& d2, float& d3,
                                         uint32_t a0, uint32_t a1, uint32_t a2, uint32_t a3,
                                         uint32_t b0, uint32_t b1) {
    asm volatile(
        "mma.sync.aligned.m16n8k16.row.col.f32.f16.f16.f32 "
        "{%0,%1,%2,%3}, {%4,%5,%6,%7}, {%8,%9}, {%0,%1,%2,%3};"
        : "+f"(d0), "+f"(d1), "+f"(d2), "+f"(d3)
        : "r"(a0), "r"(a1), "r"(a2), "r"(a3), "r"(b0), "r"(b1));
}

// ============================================================================
// Prep kernels (round-14 versions — measured best of all variants tried)
// ============================================================================
// W_eff[o][i] = nf4[code]*scale + 2 * sum_r lb[o][r]*la[r][i]  -> fp16
__global__ void __launch_bounds__(256) prep_w_kernel(
    const int* __restrict__ codes, const float* __restrict__ scales,
    const float* __restrict__ la, const float* __restrict__ lb,
    __half* __restrict__ wh) {
    __shared__ float la_s[RANK][512];
    __shared__ float lb_s[32][RANK];
    __shared__ float nf4_s[16];
    const int t  = threadIdx.x;
    const int i0 = blockIdx.x * 512;
    const int o0 = blockIdx.y * 32;
    if (t < 16) nf4_s[t] = c_nf4[t];
#pragma unroll
    for (int r = 0; r < RANK; r++)
        reinterpret_cast<float2*>(&la_s[r][0])[t] =
            reinterpret_cast<const float2*>(la + r * IN_DIM + i0)[t];
    for (int j = t; j < 32 * RANK; j += 256)
        lb_s[j >> 4][j & 15] = lb[(size_t)(o0 + (j >> 4)) * RANK + (j & 15)];
    __syncthreads();

    float2 a2[RANK];
#pragma unroll
    for (int r = 0; r < RANK; r++)
        a2[r] = reinterpret_cast<const float2*>(&la_s[r][0])[t];

    const int i = i0 + 2 * t;
#pragma unroll 2
    for (int oo = 0; oo < 32; oo++) {
        const int o = o0 + oo;
        const int2 cd = *reinterpret_cast<const int2*>(codes + (size_t)o * IN_DIM + i);
        const float s = scales[o * (IN_DIM / BLOCK_Q) + (i >> 6)];
        float ax = 0.f, ay = 0.f;
#pragma unroll
        for (int r = 0; r < RANK; r++) {
            const float b = lb_s[oo][r];
            ax = fmaf(b, a2[r].x, ax);
            ay = fmaf(b, a2[r].y, ay);
        }
        const float wx = fmaf(nf4_s[cd.x & 15], s, LORA_SCALE * ax);
        const float wy = fmaf(nf4_s[cd.y & 15], s, LORA_SCALE * ay);
        __half2 h = __floats2half2_rn(wx, wy);
        *reinterpret_cast<uint32_t*>(wh + (size_t)o * IN_DIM + i) =
            *reinterpret_cast<uint32_t*>(&h);
    }
}

// x (fp32) -> fp16; 4 independent float4 loads per thread (MLP=4).
// k-step stride of 256 float4 = 4 KB keeps each step fully coalesced.
__global__ void __launch_bounds__(256) prep_x_kernel(
    const float4* __restrict__ in, uint2* __restrict__ out) {
    const int base = blockIdx.x * (256 * PX_PER_THREAD) + threadIdx.x;
    float4 v[PX_PER_THREAD];
#pragma unroll
    for (int k = 0; k < PX_PER_THREAD; k++)
        v[k] = in[base + k * 256];
#pragma unroll
    for (int k = 0; k < PX_PER_THREAD; k++) {
        __half2 h0 = __floats2half2_rn(v[k].x, v[k].y);
        __half2 h1 = __floats2half2_rn(v[k].z, v[k].w);
        uint2 u;
        u.x = *reinterpret_cast<uint32_t*>(&h0);
        u.y = *reinterpret_cast<uint32_t*>(&h1);
        out[base + k * 256] = u;
    }
}

// ============================================================================
// GEMM: out[M, N] = Xh[M, K] @ Wh[N, K]^T   (mma.sync fp16, fp32 accum)
// TMA + mbarrier producer/consumer pipeline, proxy-fenced, lag-1 refill
// (round-10 kernel verbatim — tensor pipe 88.4%, bit-stable numerics).
// ============================================================================
__global__ void __launch_bounds__(THREADS, 2) gemm_fp16_kernel(
    const __grid_constant__ CUtensorMap mapA,
    const __grid_constant__ CUtensorMap mapB,
    float* __restrict__ out) {
    extern __shared__ char smem[];
    const uint32_t sb = smem_u32(smem);
    const uint32_t ab = (sb + 1023u) & ~1023u;          // 1KB-aligned tile base
    const uint32_t full0  = ab + STAGES * STAGE_BYTES;  // 3 x 8B
    const uint32_t empty0 = full0 + STAGES * 8;         // 3 x 8B
    const int tid  = threadIdx.x;
    const int wid  = tid >> 5;
    const int lane = tid & 31;
    const int gid  = lane >> 2;
    const int tig  = lane & 3;

    // tile swizzle for L2 reuse
    const int bid   = blockIdx.x;
    const int group = bid / (GROUP_M * TILES_N);
    const int inb   = bid % (GROUP_M * TILES_N);
    const int mtile = group * GROUP_M + (inb % GROUP_M);
    const int ntile = inb / GROUP_M;
    const int m0 = mtile * BM;
    const int n0 = ntile * BN;

    const int wm = (wid & 1) * 64;   // 2 warps along M
    const int wn = (wid >> 1) * 32;  // 4 warps along N

    if (tid == 0) {
        for (int s = 0; s < STAGES; s++) {
            MBAR_INIT(full0 + s * 8, 1);        // completes via expect_tx + tx drain
            MBAR_INIT(empty0 + s * 8, THREADS); // all threads arrive after consuming
        }
        FENCE_PROXY_ASYNC();   // order generic-proxy init stores before TMA use
    }
    __syncthreads();

    // prologue: one thread launches TMA for chunks 0..2
    if (tid == 0) {
#pragma unroll
        for (int s = 0; s < STAGES; s++) {
            uint32_t fb = full0 + s * 8;
            MBAR_EXPECT_TX(fb, STAGE_BYTES);
            tma2d(ab + s * STAGE_BYTES,                &mapA, s * BKH, m0, fb);
            tma2d(ab + s * STAGE_BYTES + A_TILE_BYTES, &mapB, s * BKH, n0, fb);
        }
    }

    // ldmatrix address precompute (offsets within a tile)
    uint32_t a_off[4], a_x[4];
#pragma unroll
    for (int mt = 0; mt < 4; mt++) {
        int r = wm + mt * 16 + (lane & 15);
        a_off[mt] = (uint32_t)(r * 128);
        a_x[mt]   = (uint32_t)(r & 7);
    }
    const uint32_t a_hi = (uint32_t)(lane >> 4);
    uint32_t b_off[2], b_x[2];
#pragma unroll
    for (int ntp = 0; ntp < 2; ntp++) {
        int r = wn + ntp * 16 + (lane & 7) + ((lane >> 4) << 3);
        b_off[ntp] = (uint32_t)(r * 128);
        b_x[ntp]   = (uint32_t)(r & 7);
    }
    const uint32_t b_hi = (uint32_t)((lane >> 3) & 1);

    float acc[4][4][4];
#pragma unroll
    for (int mt = 0; mt < 4; mt++)
#pragma unroll
        for (int nt = 0; nt < 4; nt++)
#pragma unroll
            for (int r = 0; r < 4; r++) acc[mt][nt][r] = 0.0f;

    // mainloop: stage s = c % 3, parity ph flips each wrap
    int s = 0, ph = 0;
    for (int c = 0; c < NCHUNK; c++) {
        MBAR_WAIT(full0 + s * 8, ph);

        // lag-1 producer refill: stage of chunk c-1 receives chunk c+2.
        if (tid == 0 && c >= 1 && c + 2 < NCHUNK) {
            const int pc   = c - 1;
            const int prev = pc % STAGES;
            MBAR_WAIT(empty0 + prev * 8, (pc / STAGES) & 1);
            uint32_t fb = full0 + prev * 8;
            MBAR_EXPECT_TX(fb, STAGE_BYTES);
            tma2d(ab + prev * STAGE_BYTES,                &mapA, (pc + STAGES) * BKH, m0, fb);
            tma2d(ab + prev * STAGE_BYTES + A_TILE_BYTES, &mapB, (pc + STAGES) * BKH, n0, fb);
        }

        const uint32_t As = ab + (uint32_t)(s * STAGE_BYTES);
        const uint32_t Bs = As + A_TILE_BYTES;

#pragma unroll
        for (int ks = 0; ks < BKH / 16; ks++) {
            uint32_t a_frag[4][4];
            uint32_t b_frag[4][2];
#pragma unroll
            for (int mt = 0; mt < 4; mt++) {
                uint32_t ad = As + a_off[mt] + (((2u * ks + a_hi) ^ a_x[mt]) * 16);
                LDSM_X4(a_frag[mt][0], a_frag[mt][1], a_frag[mt][2], a_frag[mt][3], ad);
            }
#pragma unroll
            for (int ntp = 0; ntp < 2; ntp++) {
                uint32_t bd = Bs + b_off[ntp] + (((2u * ks + b_hi) ^ b_x[ntp]) * 16);
                LDSM_X4(b_frag[2 * ntp][0], b_frag[2 * ntp][1],
                        b_frag[2 * ntp + 1][0], b_frag[2 * ntp + 1][1], bd);
            }
#pragma unroll
            for (int mt = 0; mt < 4; mt++)
#pragma unroll
                for (int nt = 0; nt < 4; nt++)
                    mma_fp16(acc[mt][nt][0], acc[mt][nt][1], acc[mt][nt][2], acc[mt][nt][3],
                             a_frag[mt][0], a_frag[mt][1], a_frag[mt][2], a_frag[mt][3],
                             b_frag[nt][0], b_frag[nt][1]);
        }

        // Close the generic->async proxy WAR hazard, then release the stage.
        FENCE_PROXY_ASYNC();
        MBAR_ARRIVE(empty0 + s * 8);

        if (++s == STAGES) { s = 0; ph ^= 1; }
    }

    // epilogue: row = m0+wm+mt*16+gid(+8), col = n0+wn+nt*8+tig*2
#pragma unroll
    for (int mt = 0; mt < 4; mt++) {
        const size_t r0 = (size_t)(m0 + wm + mt * 16 + gid) * OUT_DIM;
        const size_t r1 = r0 + 8 * OUT_DIM;
#pragma unroll
        for (int nt = 0; nt < 4; nt++) {
            const int col = n0 + wn + nt * 8 + tig * 2;
            *reinterpret_cast<float2*>(out + r0 + col) =
                make_float2(acc[mt][nt][0], acc[mt][nt][1]);
            *reinterpret_cast<float2*>(out + r1 + col) =
                make_float2(acc[mt][nt][2], acc[mt][nt][3]);
        }
    }
}

// ============================================================================
// Host
// ============================================================================
typedef CUresult (*EncodeFn)(CUtensorMap*, CUtensorMapDataType, cuuint32_t, void*,
                             const cuuint64_t*, const cuuint64_t*, const cuuint32_t*,
                             const cuuint32_t*, CUtensorMapInterleave, CUtensorMapSwizzle,
                             CUtensorMapL2promotion, CUtensorMapFloatOOBfill);

static EncodeFn get_encode_fn() {
    static EncodeFn fn = nullptr;
    if (!fn) {
        void* p = nullptr;
        cudaDriverEntryPointQueryResult qr;
#if CUDART_VERSION >= 12050
        cudaGetDriverEntryPointByVersion("cuTensorMapEncodeTiled", &p, 12000,
                                         cudaEnableDefault, &qr);
#else
        cudaGetDriverEntryPoint("cuTensorMapEncodeTiled", &p, cudaEnableDefault, &qr);
#endif
        fn = (EncodeFn)p;
    }
    return fn;
}

extern "C" void kernel_launch(void* const* d_in, const int* in_sizes, int n_in,
                              void* d_out, int out_size) {
    const float* x      = (const float*)d_in[0];
    const int*   codes  = (const int*)d_in[1];
    const float* scales = (const float*)d_in[2];
    const float* la     = (const float*)d_in[3];
    const float* lb     = (const float*)d_in[4];
    float* out = (float*)d_out;

    void *wptr = nullptr, *xptr = nullptr;
    cudaGetSymbolAddress(&wptr, g_wh);
    cudaGetSymbolAddress(&xptr, g_xh);

    static bool attr_set = false;
    if (!attr_set) {
        cudaFuncSetAttribute(gemm_fp16_kernel,
                             cudaFuncAttributeMaxDynamicSharedMemorySize, SMEM_ALLOC);
        attr_set = true;
    }

    // 1) fold LoRA + NF4 dequant into W_eff (fp16)
    prep_w_kernel<<<dim3(IN_DIM / 512, OUT_DIM / 32), 256>>>(
        codes, scales, la, lb, (__half*)wptr);
    // 2) x -> fp16 (MLP=4 per thread)
    prep_x_kernel<<<PX_BLOCKS, 256>>>((const float4*)x, (uint2*)xptr);

    // 3) TMA descriptors: [K, rows] fp16, box {BKH, 128}, SW128 swizzle
    EncodeFn enc = get_encode_fn();
    CUtensorMap mA, mB;
    {
        cuuint64_t dims[2]    = {IN_DIM, M_ROWS};
        cuuint64_t strides[1] = {IN_DIM * sizeof(__half)};
        cuuint32_t box[2]     = {BKH, BM};
        cuuint32_t es[2]      = {1, 1};
        enc(&mA, CU_TENSOR_MAP_DATA_TYPE_FLOAT16, 2, xptr, dims, strides, box, es,
            CU_TENSOR_MAP_INTERLEAVE_NONE, CU_TENSOR_MAP_SWIZZLE_128B,
            CU_TENSOR_MAP_L2_PROMOTION_L2_128B, CU_TENSOR_MAP_FLOAT_OOB_FILL_NONE);
    }
    {
        cuuint64_t dims[2]    = {IN_DIM, OUT_DIM};
        cuuint64_t strides[1] = {IN_DIM * sizeof(__half)};
        cuuint32_t box[2]     = {BKH, BN};
        cuuint32_t es[2]      = {1, 1};
        enc(&mB, CU_TENSOR_MAP_DATA_TYPE_FLOAT16, 2, wptr, dims, strides, box, es,
            CU_TENSOR_MAP_INTERLEAVE_NONE, CU_TENSOR_MAP_SWIZZLE_128B,
            CU_TENSOR_MAP_L2_PROMOTION_L2_128B, CU_TENSOR_MAP_FLOAT_OOB_FILL_NONE);
    }

    // 4) single large GEMM (2048 CTAs, 2 resident per SM)
    gemm_fp16_kernel<<<TILES_M * TILES_N, THREADS, SMEM_ALLOC>>>(mA, mB, out);
}